// round 11
// baseline (speedup 1.0000x reference)
#include <cuda_runtime.h>
#include <cstdint>
#include <cstddef>

#define Bsz 128
#define Tt  2048
#define Cin 16
#define CO  128
#define Hh  128
#define Gg  512

// -------- scratch (no allocations allowed; __device__ globals are the sanctioned path) ------
__device__ float g_seq[(size_t)Bsz * Tt * CO];      // conv output, [b*T+t][co]
__device__ float g_x0 [(size_t)Bsz * Tt * Gg];      // layer-0 input projection, [b*T+t][g]
__device__ float g_pooled[Bsz * Hh];                // mean over t of h1

// ---------------- packed f32x2 helpers ----------------
__device__ __forceinline__ unsigned long long fma2(unsigned long long a, unsigned long long b,
                                                   unsigned long long c) {
    unsigned long long d;
    asm("fma.rn.f32x2 %0, %1, %2, %3;" : "=l"(d) : "l"(a), "l"(b), "l"(c));
    return d;
}
__device__ __forceinline__ unsigned long long pack2(float lo, float hi) {
    unsigned long long r;
    asm("mov.b64 %0, {%1, %2};" : "=l"(r) : "f"(lo), "f"(hi));
    return r;
}
__device__ __forceinline__ void unpack2(unsigned long long v, float& a, float& b) {
    asm("mov.b64 {%0, %1}, %2;" : "=f"(a), "=f"(b) : "l"(v));
}
__device__ __forceinline__ float sum2(unsigned long long v) {
    float a, b; unpack2(v, a, b); return a + b;
}
// expand packed bf16x2 (lo16 = w[k], hi16 = w[k+1]) into f32x2 {w[k], w[k+1]}
__device__ __forceinline__ unsigned long long bf2f2(uint32_t p) {
    uint32_t lo = p << 16;
    uint32_t hi = p & 0xFFFF0000u;
    unsigned long long r;
    asm("mov.b64 %0, {%1, %2};" : "=l"(r) : "r"(lo), "r"(hi));
    return r;
}
// pack two fp32 into bf16x2 with round-to-nearest: low16 = bf16(a), high16 = bf16(b)
__device__ __forceinline__ uint32_t f2bf2(float a, float b) {
    uint32_t r;
    asm("cvt.rn.bf16x2.f32 %0, %1, %2;" : "=r"(r) : "f"(b), "f"(a));
    return r;
}

// ============================ kernel 1: conv1d(k=3,pad=1) + LeakyReLU ============================
__global__ void conv_kernel(const float* __restrict__ x, const float* __restrict__ cw,
                            const float* __restrict__ cb) {
    __shared__ float xs[130 * 16];     // t0-1 .. t0+128
    __shared__ float wct[48 * 128];    // [(c*3+kk)][co]
    __shared__ float cbs[128];
    int tid = threadIdx.x;
    int b = blockIdx.y, t0 = blockIdx.x * 128;
    for (int i = tid; i < 130 * 16; i += 256) {
        int row = i >> 4, c = i & 15;
        int t = t0 - 1 + row;
        xs[i] = (t >= 0 && t < Tt) ? x[((size_t)b * Tt + t) * Cin + c] : 0.0f;
    }
    for (int i = tid; i < 48 * 128; i += 256) {
        int co = i / 48, rem = i % 48;          // rem = c*3 + kk
        wct[rem * 128 + co] = cw[i];
    }
    if (tid < 128) cbs[tid] = cb[tid];
    __syncthreads();
    for (int idx = tid; idx < 128 * 128; idx += 256) {
        int tl = idx >> 7, co = idx & 127;
        float acc = cbs[co];
#pragma unroll
        for (int c = 0; c < 16; c++)
#pragma unroll
            for (int kk = 0; kk < 3; kk++)
                acc += xs[(tl + kk) * 16 + c] * wct[(c * 3 + kk) * 128 + co];
        acc = acc >= 0.f ? acc : 0.01f * acc;
        g_seq[((size_t)b * Tt + t0 + tl) * CO + co] = acc;
    }
}

// ============================ kernel 2: x0 = seq @ w_ih0^T + (b_ih0+b_hh0) ============================
// block tile: 128 (M) x 64 (N), K = 128 fully in smem. 256 threads, 8x4 per thread, FFMA2 inner.
#define PROJ_SMEM_BYTES ((128 * 132 + 128 * 64) * 4)
__global__ void proj_kernel(const float* __restrict__ w, const float* __restrict__ bi,
                            const float* __restrict__ bh) {
    extern __shared__ float sm[];
    float* As = sm;                 // [128][132] (padded)
    float* Ws = sm + 128 * 132;     // [k=128][n=64]
    int tid = threadIdx.x;
    int mt = blockIdx.x, nt = blockIdx.y;
    const float* Ab = g_seq + (size_t)mt * 128 * CO;
    for (int i = tid; i < 128 * 32; i += 256) {
        int row = i >> 5, c4 = i & 31;
        float4 v = reinterpret_cast<const float4*>(Ab)[(size_t)row * 32 + c4];
        float* d = As + row * 132 + c4 * 4;
        d[0] = v.x; d[1] = v.y; d[2] = v.z; d[3] = v.w;
    }
    for (int i = tid; i < 64 * 128; i += 256) {
        int n = i >> 7, k = i & 127;
        Ws[k * 64 + n] = w[(size_t)(nt * 64 + n) * CO + k];
    }
    __syncthreads();
    int ty = tid >> 4, tx = tid & 15;
    unsigned long long acc2[8][2];
#pragma unroll
    for (int i = 0; i < 8; i++) { acc2[i][0] = 0ull; acc2[i][1] = 0ull; }
#pragma unroll 2
    for (int k0 = 0; k0 < 128; k0 += 4) {
        float4 av[8];
#pragma unroll
        for (int m = 0; m < 8; m++)
            av[m] = *reinterpret_cast<const float4*>(As + (ty * 8 + m) * 132 + k0);
#pragma unroll
        for (int kk = 0; kk < 4; kk++) {
            ulonglong2 w2 = *reinterpret_cast<const ulonglong2*>(Ws + (k0 + kk) * 64 + tx * 4);
#pragma unroll
            for (int m = 0; m < 8; m++) {
                float a = (kk == 0) ? av[m].x : (kk == 1) ? av[m].y : (kk == 2) ? av[m].z : av[m].w;
                unsigned long long a2 = pack2(a, a);
                acc2[m][0] = fma2(a2, w2.x, acc2[m][0]);
                acc2[m][1] = fma2(a2, w2.y, acc2[m][1]);
            }
        }
    }
    int n0 = nt * 64 + tx * 4;
    float bb0 = bi[n0] + bh[n0], bb1 = bi[n0 + 1] + bh[n0 + 1];
    float bb2 = bi[n0 + 2] + bh[n0 + 2], bb3 = bi[n0 + 3] + bh[n0 + 3];
#pragma unroll
    for (int i = 0; i < 8; i++) {
        float4 o;
        unpack2(acc2[i][0], o.x, o.y);
        unpack2(acc2[i][1], o.z, o.w);
        o.x += bb0; o.y += bb1; o.z += bb2; o.w += bb3;
        *reinterpret_cast<float4*>(g_x0 + ((size_t)mt * 128 + ty * 8 + i) * Gg + n0) = o;
    }
}

// ============================ kernel 3: persistent 2-layer LSTM, cluster-of-4 ============================
// 32 clusters x 4 CTAs, 256 threads/CTA. Cluster owns 4 batch rows.
// CTA r owns gate rows {g*128 + r*32 + j}. Threads split the k-dim in half.
// Recurrent weights in smem as packed bf16x2; expansion via 2 ALU ops; fp32 accumulate.
// FUSED h0 pass (W_hh0.h0 and W_ih1.h0 share h loads).
// Cross-CTA sync via mbarrier phase protocol (R8-verified): after the CTA-wide
// __syncthreads orders all remote h stores, threads tid<4 release-arrive on rank
// tid's barrier (4 arrivals/barrier/phase); everyone try_waits on parity t&1.
// x0 prefetch overlaps the wait.

__device__ __forceinline__ float tanh_fast(float x) {
    float y; asm("tanh.approx.f32 %0, %1;" : "=f"(y) : "f"(x)); return y;
}
__device__ __forceinline__ float sig_fast(float x) {
    return fmaf(tanh_fast(0.5f * x), 0.5f, 0.5f);
}

// bf16 weight rows: 64 pairs + 4 pad = 68 uint32 per row
#define WROW 68
#define LSTM_SMEM_BYTES ((3 * 128 * WROW + 2048 + 2048) * 4)

__global__ void __cluster_dims__(4, 1, 1) __launch_bounds__(256, 1)
lstm_kernel(const float* __restrict__ whh0, const float* __restrict__ wih1,
            const float* __restrict__ whh1, const float* __restrict__ bih1,
            const float* __restrict__ bhh1) {
    extern __shared__ float sm[];
    uint32_t* w0 = reinterpret_cast<uint32_t*>(sm);          // W_hh0 slice [128 rows][WROW]
    uint32_t* w1 = w0 + 128 * WROW;                          // W_ih1 slice
    uint32_t* w2 = w1 + 128 * WROW;                          // W_hh1 slice
    float* hbuf = sm + 3 * 128 * WROW;                       // [2 p][2 layer][4 bb][128 k]
    float* gtmp = hbuf + 2048;                               // [2 layer][4 bb][2 half][128 row]
    __shared__ __align__(8) unsigned long long mbar[1];

    int tid = threadIdx.x;
    int half = tid >> 7;                    // k-half for GEMM; cell index for elementwise
    int wt = tid & 127, q = wt >> 5, j = wt & 31;
    uint32_t rank; asm("mov.u32 %0, %%cluster_ctarank;" : "=r"(rank));
    int r = (int)rank;
    int b0 = (blockIdx.x >> 2) * 4;
    int lr = wt;                            // local weight row
    int rowg = (q << 7) + (r << 5) + j;     // global gate row

    // load weight slices, converting fp32 -> packed bf16x2 (low16 = even k)
    for (int i = tid; i < 128 * 64; i += 256) {
        int rl = i >> 6, c = i & 63;        // row, pair index
        int rg = ((rl >> 5) << 7) + (r << 5) + (rl & 31);
        size_t gb = (size_t)rg * Hh + 2 * c;
        w0[rl * WROW + c] = f2bf2(whh0[gb], whh0[gb + 1]);
        w1[rl * WROW + c] = f2bf2(wih1[gb], wih1[gb + 1]);
        w2[rl * WROW + c] = f2bf2(whh1[gb], whh1[gb + 1]);
    }
    for (int i = tid; i < 2048; i += 256) hbuf[i] = 0.f;

    float b1init = (half == 0) ? (bih1[rowg] + bhh1[rowg]) : 0.f;

    // elementwise role: (cell=half, batch=q, h index hl)
    int hl = (r << 5) + j;
    float cst = 0.f, pool = 0.f;

    float xn[4];
    if (half == 0) {
#pragma unroll
        for (int bb = 0; bb < 4; bb++)
            xn[bb] = g_x0[((size_t)(b0 + bb) * Tt) * Gg + rowg];
    }

    // DSMEM addresses: hbuf bases on all 4 ranks, mbar base on rank tid (for tid<4)
    uint32_t hb_la = (uint32_t)__cvta_generic_to_shared(hbuf);
    uint32_t mb_la = (uint32_t)__cvta_generic_to_shared(mbar);
    uint32_t rb[4];
#pragma unroll
    for (int rk = 0; rk < 4; rk++)
        asm("mapa.shared::cluster.u32 %0, %1, %2;" : "=r"(rb[rk]) : "r"(hb_la), "r"(rk));
    uint32_t mb_rem = 0;
    if (tid < 4)
        asm("mapa.shared::cluster.u32 %0, %1, %2;" : "=r"(mb_rem) : "r"(mb_la), "r"(tid));

    if (tid == 0)
        asm volatile("mbarrier.init.shared.b64 [%0], 4;" :: "r"(mb_la) : "memory");
    __syncthreads();
    asm volatile("barrier.cluster.arrive.aligned;" ::: "memory");
    asm volatile("barrier.cluster.wait.aligned;"   ::: "memory");

    // this thread's weight row-half: 32 pairs = 8 uint4 loads per matrix
    const uint4* wr0 = reinterpret_cast<const uint4*>(w0 + lr * WROW + half * 32);
    const uint4* wr1 = reinterpret_cast<const uint4*>(w1 + lr * WROW + half * 32);
    const uint4* wr2 = reinterpret_cast<const uint4*>(w2 + lr * WROW + half * 32);

    int p = 0;
    for (int t = 0; t <= Tt; t++) {
        const float* hcur = hbuf + p * 1024 + half * 64;   // layer0 h base (+512 for layer1 h)
        unsigned long long accA[4], accB[4];
#pragma unroll
        for (int bb = 0; bb < 4; bb++) {
            accA[bb] = pack2(half == 0 ? xn[bb] : 0.f, 0.f);
            accB[bb] = pack2(b1init, 0.f);
        }
        // ---- fused h0 pass: accA += W_hh0 . h0 ; accB += W_ih1 . h0 (shared h loads)
#pragma unroll
        for (int kq = 0; kq < 8; kq++) {
            uint4 p0 = wr0[kq], p1 = wr1[kq];
            unsigned long long w0a = bf2f2(p0.x), w0b = bf2f2(p0.y),
                               w0c = bf2f2(p0.z), w0d = bf2f2(p0.w);
            unsigned long long w1a = bf2f2(p1.x), w1b = bf2f2(p1.y),
                               w1c = bf2f2(p1.z), w1d = bf2f2(p1.w);
#pragma unroll
            for (int bb = 0; bb < 4; bb++) {
                const ulonglong2* hp = reinterpret_cast<const ulonglong2*>(hcur + bb * 128) + kq * 2;
                ulonglong2 h01 = hp[0], h23 = hp[1];
                accA[bb] = fma2(w0a, h01.x, accA[bb]);
                accA[bb] = fma2(w0b, h01.y, accA[bb]);
                accA[bb] = fma2(w0c, h23.x, accA[bb]);
                accA[bb] = fma2(w0d, h23.y, accA[bb]);
                accB[bb] = fma2(w1a, h01.x, accB[bb]);
                accB[bb] = fma2(w1b, h01.y, accB[bb]);
                accB[bb] = fma2(w1c, h23.x, accB[bb]);
                accB[bb] = fma2(w1d, h23.y, accB[bb]);
            }
        }
        // ---- h1 pass: accB += W_hh1 . h1
#pragma unroll
        for (int kq = 0; kq < 8; kq++) {
            uint4 p2 = wr2[kq];
            unsigned long long w2a = bf2f2(p2.x), w2b = bf2f2(p2.y),
                               w2c = bf2f2(p2.z), w2d = bf2f2(p2.w);
#pragma unroll
            for (int bb = 0; bb < 4; bb++) {
                const ulonglong2* hp =
                    reinterpret_cast<const ulonglong2*>(hcur + 512 + bb * 128) + kq * 2;
                ulonglong2 h01 = hp[0], h23 = hp[1];
                accB[bb] = fma2(w2a, h01.x, accB[bb]);
                accB[bb] = fma2(w2b, h01.y, accB[bb]);
                accB[bb] = fma2(w2c, h23.x, accB[bb]);
                accB[bb] = fma2(w2d, h23.y, accB[bb]);
            }
        }
        if (t < Tt) {
#pragma unroll
            for (int bb = 0; bb < 4; bb++)
                gtmp[((0 + bb) * 2 + half) * 128 + lr] = sum2(accA[bb]);
        }
        if (t > 0) {
#pragma unroll
            for (int bb = 0; bb < 4; bb++)
                gtmp[((4 + bb) * 2 + half) * 128 + lr] = sum2(accB[bb]);
        }
        __syncthreads();
        // ---- elementwise: thread owns (cell=half, batch=q, h=hl)
        bool act = (half == 0) ? (t < Tt) : (t > 0);
        if (act) {
            int gb = (half * 4 + q) * 256;     // gtmp base for (layer, batch)
            float gv[4];
#pragma unroll
            for (int g = 0; g < 4; g++)
                gv[g] = gtmp[gb + (g << 5) + j] + gtmp[gb + 128 + (g << 5) + j];
            float cn = sig_fast(gv[1]) * cst + sig_fast(gv[0]) * tanh_fast(gv[2]);
            float hn = sig_fast(gv[3]) * tanh_fast(cn);
            cst = cn;
            if (half) pool += hn;
            uint32_t off = (uint32_t)((((p ^ 1) << 10) + (half << 9) + (q << 7) + hl) << 2);
#pragma unroll
            for (int rk = 0; rk < 4; rk++)
                asm volatile("st.shared::cluster.f32 [%0], %1;"
                             :: "r"(rb[rk] + off), "f"(hn) : "memory");
        }
        __syncthreads();   // orders ALL threads' remote stores before the release-arrives
        if (tid < 4)
            asm volatile("mbarrier.arrive.release.cluster.shared::cluster.b64 _, [%0];"
                         :: "r"(mb_rem) : "memory");
        // x0 prefetch overlaps peers' arrivals
        if (half == 0 && t + 1 < Tt) {
#pragma unroll
            for (int bb = 0; bb < 4; bb++)
                xn[bb] = g_x0[((size_t)(b0 + bb) * Tt + (t + 1)) * Gg + rowg];
        }
        // wait for all 4 CTAs' arrivals for this phase
        {
            uint32_t par = (uint32_t)(t & 1);
            uint32_t done;
            asm volatile(
                "{\n\t.reg .pred P;\n\t"
                "mbarrier.try_wait.parity.acquire.cluster.shared::cta.b64 P, [%1], %2;\n\t"
                "selp.b32 %0, 1, 0, P;\n\t}"
                : "=r"(done) : "r"(mb_la), "r"(par) : "memory");
            if (!done) {
                asm volatile(
                    "{\n\t.reg .pred P;\n\t"
                    "WL_%=:\n\t"
                    "mbarrier.try_wait.parity.acquire.cluster.shared::cta.b64 P, [%0], %1, 0x989680;\n\t"
                    "@P bra.uni WD_%=;\n\t"
                    "bra.uni WL_%=;\n\t"
                    "WD_%=:\n\t}"
                    :: "r"(mb_la), "r"(par) : "memory");
            }
        }
        p ^= 1;
    }
    if (half == 1)
        g_pooled[(size_t)(b0 + q) * Hh + hl] = pool * (1.0f / 2048.0f);
    // keep CTAs resident until every peer is past its last remote store
    asm volatile("barrier.cluster.arrive.aligned;" ::: "memory");
    asm volatile("barrier.cluster.wait.aligned;"   ::: "memory");
}

// ============================ kernel 4: out[b] = pooled[b,:] . lin_w + lin_b ============================
__global__ void final_kernel(const float* __restrict__ lw, const float* __restrict__ lb,
                             float* __restrict__ out) {
    int b = threadIdx.x;
    float acc = lb[0];
#pragma unroll 8
    for (int h = 0; h < Hh; h++) acc += g_pooled[b * Hh + h] * lw[h];
    out[b] = acc;
}

// ============================ launch ============================
extern "C" void kernel_launch(void* const* d_in, const int* in_sizes, int n_in,
                              void* d_out, int out_size) {
    (void)in_sizes; (void)n_in; (void)out_size;
    const float* x      = (const float*)d_in[0];
    const float* conv_w = (const float*)d_in[1];
    const float* conv_b = (const float*)d_in[2];
    const float* w_ih0  = (const float*)d_in[3];
    const float* w_hh0  = (const float*)d_in[4];
    const float* b_ih0  = (const float*)d_in[5];
    const float* b_hh0  = (const float*)d_in[6];
    const float* w_ih1  = (const float*)d_in[7];
    const float* w_hh1  = (const float*)d_in[8];
    const float* b_ih1  = (const float*)d_in[9];
    const float* b_hh1  = (const float*)d_in[10];
    const float* lin_w  = (const float*)d_in[11];
    const float* lin_b  = (const float*)d_in[12];
    float* out = (float*)d_out;

    cudaFuncSetAttribute(proj_kernel, cudaFuncAttributeMaxDynamicSharedMemorySize, PROJ_SMEM_BYTES);
    cudaFuncSetAttribute(lstm_kernel, cudaFuncAttributeMaxDynamicSharedMemorySize, LSTM_SMEM_BYTES);

    conv_kernel<<<dim3(Tt / 128, Bsz), 256>>>(x, conv_w, conv_b);
    proj_kernel<<<dim3((Bsz * Tt) / 128, Gg / 64), 256, PROJ_SMEM_BYTES>>>(w_ih0, b_ih0, b_hh0);
    lstm_kernel<<<128, 256, LSTM_SMEM_BYTES>>>(w_hh0, w_ih1, w_hh1, b_ih1, b_hh1);
    final_kernel<<<1, 128>>>(lin_w, lin_b, out);
}

// round 14
// speedup vs baseline: 1.0491x; 1.0491x over previous
#include <cuda_runtime.h>
#include <cstdint>
#include <cstddef>

#define Bsz 128
#define Tt  2048
#define Cin 16
#define CO  128
#define Hh  128
#define Gg  512

// -------- scratch (no allocations allowed; __device__ globals are the sanctioned path) ------
__device__ float g_seq[(size_t)Bsz * Tt * CO];      // conv output, [b*T+t][co]
__device__ float g_x0 [(size_t)Bsz * Tt * Gg];      // layer-0 input projection, [b*T+t][g]
__device__ float g_pooled[Bsz * Hh];                // mean over t of h1

// ---------------- packed f32x2 helpers ----------------
__device__ __forceinline__ unsigned long long fma2(unsigned long long a, unsigned long long b,
                                                   unsigned long long c) {
    unsigned long long d;
    asm("fma.rn.f32x2 %0, %1, %2, %3;" : "=l"(d) : "l"(a), "l"(b), "l"(c));
    return d;
}
__device__ __forceinline__ unsigned long long pack2(float lo, float hi) {
    unsigned long long r;
    asm("mov.b64 %0, {%1, %2};" : "=l"(r) : "f"(lo), "f"(hi));
    return r;
}
__device__ __forceinline__ void unpack2(unsigned long long v, float& a, float& b) {
    asm("mov.b64 {%0, %1}, %2;" : "=f"(a), "=f"(b) : "l"(v));
}
__device__ __forceinline__ float sum2(unsigned long long v) {
    float a, b; unpack2(v, a, b); return a + b;
}
// expand packed bf16x2 (lo16 = w[k], hi16 = w[k+1]) into f32x2 {w[k], w[k+1]}
__device__ __forceinline__ unsigned long long bf2f2(uint32_t p) {
    uint32_t lo = p << 16;
    uint32_t hi = p & 0xFFFF0000u;
    unsigned long long r;
    asm("mov.b64 %0, {%1, %2};" : "=l"(r) : "r"(lo), "r"(hi));
    return r;
}
// pack two fp32 into bf16x2 with round-to-nearest: low16 = bf16(a), high16 = bf16(b)
__device__ __forceinline__ uint32_t f2bf2(float a, float b) {
    uint32_t r;
    asm("cvt.rn.bf16x2.f32 %0, %1, %2;" : "=r"(r) : "f"(b), "f"(a));
    return r;
}

// ============================ kernel 1: conv1d(k=3,pad=1) + LeakyReLU ============================
__global__ void conv_kernel(const float* __restrict__ x, const float* __restrict__ cw,
                            const float* __restrict__ cb) {
    __shared__ float xs[130 * 16];     // t0-1 .. t0+128
    __shared__ float wct[48 * 128];    // [(c*3+kk)][co]
    __shared__ float cbs[128];
    int tid = threadIdx.x;
    int b = blockIdx.y, t0 = blockIdx.x * 128;
    for (int i = tid; i < 130 * 16; i += 256) {
        int row = i >> 4, c = i & 15;
        int t = t0 - 1 + row;
        xs[i] = (t >= 0 && t < Tt) ? x[((size_t)b * Tt + t) * Cin + c] : 0.0f;
    }
    for (int i = tid; i < 48 * 128; i += 256) {
        int co = i / 48, rem = i % 48;          // rem = c*3 + kk
        wct[rem * 128 + co] = cw[i];
    }
    if (tid < 128) cbs[tid] = cb[tid];
    __syncthreads();
    for (int idx = tid; idx < 128 * 128; idx += 256) {
        int tl = idx >> 7, co = idx & 127;
        float acc = cbs[co];
#pragma unroll
        for (int c = 0; c < 16; c++)
#pragma unroll
            for (int kk = 0; kk < 3; kk++)
                acc += xs[(tl + kk) * 16 + c] * wct[(c * 3 + kk) * 128 + co];
        acc = acc >= 0.f ? acc : 0.01f * acc;
        g_seq[((size_t)b * Tt + t0 + tl) * CO + co] = acc;
    }
}

// ============================ kernel 2: x0 = seq @ w_ih0^T + (b_ih0+b_hh0) ============================
// block tile: 128 (M) x 64 (N), K = 128 fully in smem. 256 threads, 8x4 per thread, FFMA2 inner.
#define PROJ_SMEM_BYTES ((128 * 132 + 128 * 64) * 4)
__global__ void proj_kernel(const float* __restrict__ w, const float* __restrict__ bi,
                            const float* __restrict__ bh) {
    extern __shared__ float sm[];
    float* As = sm;                 // [128][132] (padded)
    float* Ws = sm + 128 * 132;     // [k=128][n=64]
    int tid = threadIdx.x;
    int mt = blockIdx.x, nt = blockIdx.y;
    const float* Ab = g_seq + (size_t)mt * 128 * CO;
    for (int i = tid; i < 128 * 32; i += 256) {
        int row = i >> 5, c4 = i & 31;
        float4 v = reinterpret_cast<const float4*>(Ab)[(size_t)row * 32 + c4];
        float* d = As + row * 132 + c4 * 4;
        d[0] = v.x; d[1] = v.y; d[2] = v.z; d[3] = v.w;
    }
    for (int i = tid; i < 64 * 128; i += 256) {
        int n = i >> 7, k = i & 127;
        Ws[k * 64 + n] = w[(size_t)(nt * 64 + n) * CO + k];
    }
    __syncthreads();
    int ty = tid >> 4, tx = tid & 15;
    unsigned long long acc2[8][2];
#pragma unroll
    for (int i = 0; i < 8; i++) { acc2[i][0] = 0ull; acc2[i][1] = 0ull; }
#pragma unroll 2
    for (int k0 = 0; k0 < 128; k0 += 4) {
        float4 av[8];
#pragma unroll
        for (int m = 0; m < 8; m++)
            av[m] = *reinterpret_cast<const float4*>(As + (ty * 8 + m) * 132 + k0);
#pragma unroll
        for (int kk = 0; kk < 4; kk++) {
            ulonglong2 w2 = *reinterpret_cast<const ulonglong2*>(Ws + (k0 + kk) * 64 + tx * 4);
#pragma unroll
            for (int m = 0; m < 8; m++) {
                float a = (kk == 0) ? av[m].x : (kk == 1) ? av[m].y : (kk == 2) ? av[m].z : av[m].w;
                unsigned long long a2 = pack2(a, a);
                acc2[m][0] = fma2(a2, w2.x, acc2[m][0]);
                acc2[m][1] = fma2(a2, w2.y, acc2[m][1]);
            }
        }
    }
    int n0 = nt * 64 + tx * 4;
    float bb0 = bi[n0] + bh[n0], bb1 = bi[n0 + 1] + bh[n0 + 1];
    float bb2 = bi[n0 + 2] + bh[n0 + 2], bb3 = bi[n0 + 3] + bh[n0 + 3];
#pragma unroll
    for (int i = 0; i < 8; i++) {
        float4 o;
        unpack2(acc2[i][0], o.x, o.y);
        unpack2(acc2[i][1], o.z, o.w);
        o.x += bb0; o.y += bb1; o.z += bb2; o.w += bb3;
        *reinterpret_cast<float4*>(g_x0 + ((size_t)mt * 128 + ty * 8 + i) * Gg + n0) = o;
    }
}

// ============================ kernel 3: persistent 2-layer LSTM, cluster-of-4 ============================
// 32 clusters x 4 CTAs, 512 threads/CTA (4 warps/SMSP for latency hiding).
// Cluster owns 4 batch rows. CTA r owns gate rows {g*128 + r*32 + j}; threads split
// the k-dim in QUARTERS (32 k each). Weights in smem as packed bf16x2 (ALU expand,
// fp32 fma2 accumulate). FUSED h0 pass shares h loads between W_hh0 and W_ih1.
// gtmp holds 4 partials per gate row; elementwise (256 active threads) combines them.
// Sync: barrier.cluster per step (R10-proven); x0 prefetch overlaps arrive->wait.

__device__ __forceinline__ float tanh_fast(float x) {
    float y; asm("tanh.approx.f32 %0, %1;" : "=f"(y) : "f"(x)); return y;
}
__device__ __forceinline__ float sig_fast(float x) {
    return fmaf(tanh_fast(0.5f * x), 0.5f, 0.5f);
}

// bf16 weight rows: 64 pairs + 4 pad = 68 uint32 per row
#define WROW 68
// smem: weights 3*128*68 u32 | hbuf 2048 f32 | gtmp 4096 f32 ([2 L][4 bb][4 qt][128 row])
#define LSTM_SMEM_BYTES ((3 * 128 * WROW + 2048 + 4096) * 4)

__global__ void __cluster_dims__(4, 1, 1) __launch_bounds__(512, 1)
lstm_kernel(const float* __restrict__ whh0, const float* __restrict__ wih1,
            const float* __restrict__ whh1, const float* __restrict__ bih1,
            const float* __restrict__ bhh1) {
    extern __shared__ float sm[];
    uint32_t* w0 = reinterpret_cast<uint32_t*>(sm);          // W_hh0 slice [128 rows][WROW]
    uint32_t* w1 = w0 + 128 * WROW;                          // W_ih1 slice
    uint32_t* w2 = w1 + 128 * WROW;                          // W_hh1 slice
    float* hbuf = sm + 3 * 128 * WROW;                       // [2 p][2 layer][4 bb][128 k]
    float* gtmp = hbuf + 2048;                               // [2 L][4 bb][4 qt][128 row]

    int tid = threadIdx.x;
    int qt = tid >> 7;                       // k-quarter for GEMM role (0..3)
    int wt = tid & 127;                      // local gate row
    uint32_t rank; asm("mov.u32 %0, %%cluster_ctarank;" : "=r"(rank));
    int r = (int)rank;
    int b0 = (blockIdx.x >> 2) * 4;
    int lr = wt;
    int rowg = ((wt >> 5) << 7) + (r << 5) + (wt & 31);   // global gate row (GEMM role)

    // load weight slices, converting fp32 -> packed bf16x2 (low16 = even k)
    for (int i = tid; i < 128 * 64; i += 512) {
        int rl = i >> 6, c = i & 63;        // row, pair index
        int rg = ((rl >> 5) << 7) + (r << 5) + (rl & 31);
        size_t gb = (size_t)rg * Hh + 2 * c;
        w0[rl * WROW + c] = f2bf2(whh0[gb], whh0[gb + 1]);
        w1[rl * WROW + c] = f2bf2(wih1[gb], wih1[gb + 1]);
        w2[rl * WROW + c] = f2bf2(whh1[gb], whh1[gb + 1]);
    }
    for (int i = tid; i < 2048; i += 512) hbuf[i] = 0.f;

    float b1init = (qt == 0) ? (bih1[rowg] + bhh1[rowg]) : 0.f;

    // elementwise role: threads 0..255 own cells (layer=half, batch=q, h=hl)
    int half = (tid >> 7) & 1;              // valid for tid < 256
    int q = (tid >> 5) & 3, j = tid & 31;
    int hl = (r << 5) + j;
    bool ew = (tid < 256);
    float cst = 0.f, pool = 0.f;

    float xn[4];
    if (qt == 0) {
#pragma unroll
        for (int bb = 0; bb < 4; bb++)
            xn[bb] = g_x0[((size_t)(b0 + bb) * Tt) * Gg + rowg];
    }

    // precompute remote DSMEM base addresses for all 4 ranks
    uint32_t hb_la = (uint32_t)__cvta_generic_to_shared(hbuf);
    uint32_t rb[4];
#pragma unroll
    for (int rk = 0; rk < 4; rk++)
        asm("mapa.shared::cluster.u32 %0, %1, %2;" : "=r"(rb[rk]) : "r"(hb_la), "r"(rk));

    __syncthreads();
    asm volatile("barrier.cluster.arrive.aligned;" ::: "memory");
    asm volatile("barrier.cluster.wait.aligned;"   ::: "memory");

    // this thread's weight row-quarter: 16 pairs = 4 uint4 loads per matrix
    const uint4* wr0 = reinterpret_cast<const uint4*>(w0 + lr * WROW + qt * 16);
    const uint4* wr1 = reinterpret_cast<const uint4*>(w1 + lr * WROW + qt * 16);
    const uint4* wr2 = reinterpret_cast<const uint4*>(w2 + lr * WROW + qt * 16);

    int p = 0;
    for (int t = 0; t <= Tt; t++) {
        const float* hcur = hbuf + p * 1024 + qt * 32;     // layer0 h base (+512 for layer1 h)
        unsigned long long accA[4], accB[4];
#pragma unroll
        for (int bb = 0; bb < 4; bb++) {
            accA[bb] = pack2(qt == 0 ? xn[bb] : 0.f, 0.f);
            accB[bb] = pack2(b1init, 0.f);
        }
        // ---- fused h0 pass: accA += W_hh0 . h0 ; accB += W_ih1 . h0 (shared h loads)
#pragma unroll
        for (int kq = 0; kq < 4; kq++) {
            uint4 p0 = wr0[kq], p1 = wr1[kq];
            unsigned long long w0a = bf2f2(p0.x), w0b = bf2f2(p0.y),
                               w0c = bf2f2(p0.z), w0d = bf2f2(p0.w);
            unsigned long long w1a = bf2f2(p1.x), w1b = bf2f2(p1.y),
                               w1c = bf2f2(p1.z), w1d = bf2f2(p1.w);
#pragma unroll
            for (int bb = 0; bb < 4; bb++) {
                const ulonglong2* hp = reinterpret_cast<const ulonglong2*>(hcur + bb * 128) + kq * 2;
                ulonglong2 h01 = hp[0], h23 = hp[1];
                accA[bb] = fma2(w0a, h01.x, accA[bb]);
                accA[bb] = fma2(w0b, h01.y, accA[bb]);
                accA[bb] = fma2(w0c, h23.x, accA[bb]);
                accA[bb] = fma2(w0d, h23.y, accA[bb]);
                accB[bb] = fma2(w1a, h01.x, accB[bb]);
                accB[bb] = fma2(w1b, h01.y, accB[bb]);
                accB[bb] = fma2(w1c, h23.x, accB[bb]);
                accB[bb] = fma2(w1d, h23.y, accB[bb]);
            }
        }
        // ---- h1 pass: accB += W_hh1 . h1
#pragma unroll
        for (int kq = 0; kq < 4; kq++) {
            uint4 p2 = wr2[kq];
            unsigned long long w2a = bf2f2(p2.x), w2b = bf2f2(p2.y),
                               w2c = bf2f2(p2.z), w2d = bf2f2(p2.w);
#pragma unroll
            for (int bb = 0; bb < 4; bb++) {
                const ulonglong2* hp =
                    reinterpret_cast<const ulonglong2*>(hcur + 512 + bb * 128) + kq * 2;
                ulonglong2 h01 = hp[0], h23 = hp[1];
                accB[bb] = fma2(w2a, h01.x, accB[bb]);
                accB[bb] = fma2(w2b, h01.y, accB[bb]);
                accB[bb] = fma2(w2c, h23.x, accB[bb]);
                accB[bb] = fma2(w2d, h23.y, accB[bb]);
            }
        }
        if (t < Tt) {
#pragma unroll
            for (int bb = 0; bb < 4; bb++)
                gtmp[(bb << 9) + (qt << 7) + lr] = sum2(accA[bb]);
        }
        if (t > 0) {
#pragma unroll
            for (int bb = 0; bb < 4; bb++)
                gtmp[2048 + (bb << 9) + (qt << 7) + lr] = sum2(accB[bb]);
        }
        __syncthreads();
        // ---- elementwise: threads 0..255, thread owns (layer=half, batch=q, h=hl)
        bool act = ew && ((half == 0) ? (t < Tt) : (t > 0));
        if (act) {
            int gb = half * 2048 + (q << 9);   // gtmp base for (layer, batch)
            float gv[4];
#pragma unroll
            for (int g = 0; g < 4; g++) {
                int ro = (g << 5) + j;
                gv[g] = (gtmp[gb + ro] + gtmp[gb + 128 + ro])
                      + (gtmp[gb + 256 + ro] + gtmp[gb + 384 + ro]);
            }
            float cn = sig_fast(gv[1]) * cst + sig_fast(gv[0]) * tanh_fast(gv[2]);
            float hn = sig_fast(gv[3]) * tanh_fast(cn);
            cst = cn;
            if (half) pool += hn;
            uint32_t off = (uint32_t)((((p ^ 1) << 10) + (half << 9) + (q << 7) + hl) << 2);
#pragma unroll
            for (int rk = 0; rk < 4; rk++)
                asm volatile("st.shared::cluster.f32 [%0], %1;"
                             :: "r"(rb[rk] + off), "f"(hn) : "memory");
        }
        asm volatile("barrier.cluster.arrive.aligned;" ::: "memory");
        if (qt == 0 && t + 1 < Tt) {
#pragma unroll
            for (int bb = 0; bb < 4; bb++)
                xn[bb] = g_x0[((size_t)(b0 + bb) * Tt + (t + 1)) * Gg + rowg];
        }
        asm volatile("barrier.cluster.wait.aligned;" ::: "memory");
        p ^= 1;
    }
    if (ew && half == 1)
        g_pooled[(size_t)(b0 + q) * Hh + hl] = pool * (1.0f / 2048.0f);
}

// ============================ kernel 4: out[b] = pooled[b,:] . lin_w + lin_b ============================
__global__ void final_kernel(const float* __restrict__ lw, const float* __restrict__ lb,
                             float* __restrict__ out) {
    int b = threadIdx.x;
    float acc = lb[0];
#pragma unroll 8
    for (int h = 0; h < Hh; h++) acc += g_pooled[b * Hh + h] * lw[h];
    out[b] = acc;
}

// ============================ launch ============================
extern "C" void kernel_launch(void* const* d_in, const int* in_sizes, int n_in,
                              void* d_out, int out_size) {
    (void)in_sizes; (void)n_in; (void)out_size;
    const float* x      = (const float*)d_in[0];
    const float* conv_w = (const float*)d_in[1];
    const float* conv_b = (const float*)d_in[2];
    const float* w_ih0  = (const float*)d_in[3];
    const float* w_hh0  = (const float*)d_in[4];
    const float* b_ih0  = (const float*)d_in[5];
    const float* b_hh0  = (const float*)d_in[6];
    const float* w_ih1  = (const float*)d_in[7];
    const float* w_hh1  = (const float*)d_in[8];
    const float* b_ih1  = (const float*)d_in[9];
    const float* b_hh1  = (const float*)d_in[10];
    const float* lin_w  = (const float*)d_in[11];
    const float* lin_b  = (const float*)d_in[12];
    float* out = (float*)d_out;

    cudaFuncSetAttribute(proj_kernel, cudaFuncAttributeMaxDynamicSharedMemorySize, PROJ_SMEM_BYTES);
    cudaFuncSetAttribute(lstm_kernel, cudaFuncAttributeMaxDynamicSharedMemorySize, LSTM_SMEM_BYTES);

    conv_kernel<<<dim3(Tt / 128, Bsz), 256>>>(x, conv_w, conv_b);
    proj_kernel<<<dim3((Bsz * Tt) / 128, Gg / 64), 256, PROJ_SMEM_BYTES>>>(w_ih0, b_ih0, b_hh0);
    lstm_kernel<<<128, 512, LSTM_SMEM_BYTES>>>(w_hh0, w_ih1, w_hh1, b_ih1, b_hh1);
    final_kernel<<<1, 128>>>(lin_w, lin_b, out);
}

// round 16
// speedup vs baseline: 1.2579x; 1.1991x over previous
#include <cuda_runtime.h>
#include <cstdint>
#include <cstddef>

#define Bsz 128
#define Tt  2048
#define Cin 16
#define CO  128
#define Hh  128
#define Gg  512

// -------- scratch (no allocations allowed; __device__ globals are the sanctioned path) ------
__device__ uint32_t g_seq16[(size_t)Bsz * Tt * 64];   // conv output, f16x2 pairs [b*T+t][co/2]
__device__ uint32_t g_w16[Gg * 64];                   // w_ih0 as f16x2 [g][k/2]
__device__ float    g_bsum[Gg];                       // b_ih0 + b_hh0
__device__ float g_x0 [(size_t)Bsz * Tt * Gg];        // layer-0 input projection, [b*T+t][g]
__device__ float g_pooled[Bsz * Hh];                  // mean over t of h1

// ---------------- packed f32x2 helpers ----------------
__device__ __forceinline__ unsigned long long fma2(unsigned long long a, unsigned long long b,
                                                   unsigned long long c) {
    unsigned long long d;
    asm("fma.rn.f32x2 %0, %1, %2, %3;" : "=l"(d) : "l"(a), "l"(b), "l"(c));
    return d;
}
__device__ __forceinline__ unsigned long long pack2(float lo, float hi) {
    unsigned long long r;
    asm("mov.b64 %0, {%1, %2};" : "=l"(r) : "f"(lo), "f"(hi));
    return r;
}
__device__ __forceinline__ void unpack2(unsigned long long v, float& a, float& b) {
    asm("mov.b64 {%0, %1}, %2;" : "=f"(a), "=f"(b) : "l"(v));
}
__device__ __forceinline__ float sum2(unsigned long long v) {
    float a, b; unpack2(v, a, b); return a + b;
}
// expand packed bf16x2 into f32x2 {w[k], w[k+1]}
__device__ __forceinline__ unsigned long long bf2f2(uint32_t p) {
    uint32_t lo = p << 16;
    uint32_t hi = p & 0xFFFF0000u;
    unsigned long long r;
    asm("mov.b64 %0, {%1, %2};" : "=l"(r) : "r"(lo), "r"(hi));
    return r;
}
// pack two fp32 into bf16x2: low16 = bf16(a), high16 = bf16(b)
__device__ __forceinline__ uint32_t f2bf2(float a, float b) {
    uint32_t r;
    asm("cvt.rn.bf16x2.f32 %0, %1, %2;" : "=r"(r) : "f"(b), "f"(a));
    return r;
}
// pack two fp32 into f16x2: low16 = f16(a), high16 = f16(b)
__device__ __forceinline__ uint32_t f2h2(float a, float b) {
    uint32_t r;
    asm("cvt.rn.f16x2.f32 %0, %1, %2;" : "=r"(r) : "f"(b), "f"(a));
    return r;
}

// ============================ kernel 1: conv1d(k=3,pad=1) + LeakyReLU -> f16 ============================
__global__ void conv_kernel(const float* __restrict__ x, const float* __restrict__ cw,
                            const float* __restrict__ cb) {
    __shared__ float xs[130 * 16];     // t0-1 .. t0+128
    __shared__ float wct[48 * 128];    // [(c*3+kk)][co]
    __shared__ float cbs[128];
    int tid = threadIdx.x;
    int b = blockIdx.y, t0 = blockIdx.x * 128;
    for (int i = tid; i < 130 * 16; i += 256) {
        int row = i >> 4, c = i & 15;
        int t = t0 - 1 + row;
        xs[i] = (t >= 0 && t < Tt) ? x[((size_t)b * Tt + t) * Cin + c] : 0.0f;
    }
    for (int i = tid; i < 48 * 128; i += 256) {
        int co = i / 48, rem = i % 48;          // rem = c*3 + kk
        wct[rem * 128 + co] = cw[i];
    }
    if (tid < 128) cbs[tid] = cb[tid];
    __syncthreads();
    for (int idx = tid; idx < 128 * 64; idx += 256) {
        int tl = idx >> 6, cp = idx & 63;
        int co0 = 2 * cp, co1 = 2 * cp + 1;
        float a0 = cbs[co0], a1 = cbs[co1];
#pragma unroll
        for (int c = 0; c < 16; c++)
#pragma unroll
            for (int kk = 0; kk < 3; kk++) {
                float xv = xs[(tl + kk) * 16 + c];
                a0 += xv * wct[(c * 3 + kk) * 128 + co0];
                a1 += xv * wct[(c * 3 + kk) * 128 + co1];
            }
        a0 = a0 >= 0.f ? a0 : 0.01f * a0;
        a1 = a1 >= 0.f ? a1 : 0.01f * a1;
        g_seq16[((size_t)b * Tt + t0 + tl) * 64 + cp] = f2h2(a0, a1);
    }
}

// ============================ kernel 1b: w_ih0 -> f16, bias sum ============================
__global__ void prep_kernel(const float* __restrict__ w, const float* __restrict__ bi,
                            const float* __restrict__ bh) {
    int i = blockIdx.x * 256 + threadIdx.x;      // 0 .. 32767
    if (i < Gg * 64) {
        int n = i >> 6, cp = i & 63;
        const float* s = w + (size_t)n * CO + 2 * cp;
        g_w16[i] = f2h2(s[0], s[1]);
    }
    if (i < Gg) g_bsum[i] = bi[i] + bh[i];
}

// ============================ kernel 2: x0 = seq @ w_ih0^T + bsum  (HMMA) ============================
// tile 128(M) x 64(N), K=128 in smem (f16, row stride 68 u32 = 17*16B, conflict-free ldmatrix).
// 256 threads = 8 warps: warp (wid&3) -> m32 block, (wid>>2) -> n32 block.
// per warp: 2 m16 frags x 4 n8 frags x 8 k16 steps of mma.sync.m16n8k16.f32.f16.f16.f32.
#define PROJ_SMEM_BYTES ((128 * 68 + 64 * 68) * 4 + 256)
__global__ void proj_kernel(void) {
    extern __shared__ uint32_t smu[];
    uint32_t* As = smu;                      // [128][68]
    uint32_t* Ws = smu + 128 * 68;           // [64][68]
    float* bsum_s = reinterpret_cast<float*>(smu + 128 * 68 + 64 * 68);
    int tid = threadIdx.x;
    int mt = blockIdx.x, nt = blockIdx.y;

    const uint4* a4 = reinterpret_cast<const uint4*>(g_seq16 + (size_t)mt * 128 * 64);
    for (int i = tid; i < 128 * 16; i += 256) {
        int row = i >> 4, c4 = i & 15;
        uint4 v = a4[row * 16 + c4];
        uint32_t* d = As + row * 68 + c4 * 4;
        d[0] = v.x; d[1] = v.y; d[2] = v.z; d[3] = v.w;
    }
    const uint4* w4 = reinterpret_cast<const uint4*>(g_w16 + (size_t)nt * 64 * 64);
    for (int i = tid; i < 64 * 16; i += 256) {
        int row = i >> 4, c4 = i & 15;
        uint4 v = w4[row * 16 + c4];
        uint32_t* d = Ws + row * 68 + c4 * 4;
        d[0] = v.x; d[1] = v.y; d[2] = v.z; d[3] = v.w;
    }
    if (tid < 64) bsum_s[tid] = g_bsum[nt * 64 + tid];
    __syncthreads();

    int lane = tid & 31, wid = tid >> 5;
    int wm = (wid & 3) * 32, wn = (wid >> 2) * 32;
    uint32_t as_b = (uint32_t)__cvta_generic_to_shared(As);
    uint32_t ws_b = (uint32_t)__cvta_generic_to_shared(Ws);
    // byte addresses; row stride = 68*4 = 272 B
    uint32_t a_ad[2];
#pragma unroll
    for (int mf = 0; mf < 2; mf++)
        a_ad[mf] = as_b + (wm + mf * 16 + (lane & 15)) * 272 + (lane >> 4) * 16;
    uint32_t b_ad[4];
#pragma unroll
    for (int nf = 0; nf < 4; nf++)
        b_ad[nf] = ws_b + (wn + nf * 8 + (lane & 7)) * 272 + ((lane >> 3) & 1) * 16;

    float acc[2][4][4];
#pragma unroll
    for (int mf = 0; mf < 2; mf++)
#pragma unroll
        for (int nf = 0; nf < 4; nf++)
#pragma unroll
            for (int i = 0; i < 4; i++) acc[mf][nf][i] = 0.f;

#pragma unroll
    for (int ks = 0; ks < 8; ks++) {
        uint32_t a[2][4];
#pragma unroll
        for (int mf = 0; mf < 2; mf++)
            asm volatile("ldmatrix.sync.aligned.m8n8.x4.shared.b16 {%0,%1,%2,%3}, [%4];"
                         : "=r"(a[mf][0]), "=r"(a[mf][1]), "=r"(a[mf][2]), "=r"(a[mf][3])
                         : "r"(a_ad[mf] + ks * 32));
        uint32_t bf[4][2];
#pragma unroll
        for (int nf = 0; nf < 4; nf++)
            asm volatile("ldmatrix.sync.aligned.m8n8.x2.shared.b16 {%0,%1}, [%2];"
                         : "=r"(bf[nf][0]), "=r"(bf[nf][1])
                         : "r"(b_ad[nf] + ks * 32));
#pragma unroll
        for (int mf = 0; mf < 2; mf++)
#pragma unroll
            for (int nf = 0; nf < 4; nf++)
                asm volatile(
                    "mma.sync.aligned.m16n8k16.row.col.f32.f16.f16.f32 "
                    "{%0,%1,%2,%3}, {%4,%5,%6,%7}, {%8,%9}, {%0,%1,%2,%3};"
                    : "+f"(acc[mf][nf][0]), "+f"(acc[mf][nf][1]),
                      "+f"(acc[mf][nf][2]), "+f"(acc[mf][nf][3])
                    : "r"(a[mf][0]), "r"(a[mf][1]), "r"(a[mf][2]), "r"(a[mf][3]),
                      "r"(bf[nf][0]), "r"(bf[nf][1]));
    }

    int g = lane >> 2, t = lane & 3;
#pragma unroll
    for (int mf = 0; mf < 2; mf++) {
        int row0 = mt * 128 + wm + mf * 16 + g;
#pragma unroll
        for (int nf = 0; nf < 4; nf++) {
            int nl = wn + nf * 8 + t * 2;
            float b0 = bsum_s[nl], b1 = bsum_s[nl + 1];
            int nglob = nt * 64 + nl;
            float2 v0 = { acc[mf][nf][0] + b0, acc[mf][nf][1] + b1 };
            float2 v1 = { acc[mf][nf][2] + b0, acc[mf][nf][3] + b1 };
            *reinterpret_cast<float2*>(g_x0 + (size_t)row0 * Gg + nglob) = v0;
            *reinterpret_cast<float2*>(g_x0 + (size_t)(row0 + 8) * Gg + nglob) = v1;
        }
    }
}

// ============================ kernel 3: persistent 2-layer LSTM, cluster-of-4 ============================
// (unchanged from R14 @ 5855us: 32 clusters x 4 CTAs, 512 thr, bf16x2 smem weights,
//  fused h0 pass, k-quarters, gtmp 4-partials, barrier.cluster per step)

__device__ __forceinline__ float tanh_fast(float x) {
    float y; asm("tanh.approx.f32 %0, %1;" : "=f"(y) : "f"(x)); return y;
}
__device__ __forceinline__ float sig_fast(float x) {
    return fmaf(tanh_fast(0.5f * x), 0.5f, 0.5f);
}

#define WROW 68
#define LSTM_SMEM_BYTES ((3 * 128 * WROW + 2048 + 4096) * 4)

__global__ void __cluster_dims__(4, 1, 1) __launch_bounds__(512, 1)
lstm_kernel(const float* __restrict__ whh0, const float* __restrict__ wih1,
            const float* __restrict__ whh1, const float* __restrict__ bih1,
            const float* __restrict__ bhh1) {
    extern __shared__ float sm[];
    uint32_t* w0 = reinterpret_cast<uint32_t*>(sm);          // W_hh0 slice [128 rows][WROW]
    uint32_t* w1 = w0 + 128 * WROW;                          // W_ih1 slice
    uint32_t* w2 = w1 + 128 * WROW;                          // W_hh1 slice
    float* hbuf = sm + 3 * 128 * WROW;                       // [2 p][2 layer][4 bb][128 k]
    float* gtmp = hbuf + 2048;                               // [2 L][4 bb][4 qt][128 row]

    int tid = threadIdx.x;
    int qt = tid >> 7;
    int wt = tid & 127;
    uint32_t rank; asm("mov.u32 %0, %%cluster_ctarank;" : "=r"(rank));
    int r = (int)rank;
    int b0 = (blockIdx.x >> 2) * 4;
    int lr = wt;
    int rowg = ((wt >> 5) << 7) + (r << 5) + (wt & 31);

    for (int i = tid; i < 128 * 64; i += 512) {
        int rl = i >> 6, c = i & 63;
        int rg = ((rl >> 5) << 7) + (r << 5) + (rl & 31);
        size_t gb = (size_t)rg * Hh + 2 * c;
        w0[rl * WROW + c] = f2bf2(whh0[gb], whh0[gb + 1]);
        w1[rl * WROW + c] = f2bf2(wih1[gb], wih1[gb + 1]);
        w2[rl * WROW + c] = f2bf2(whh1[gb], whh1[gb + 1]);
    }
    for (int i = tid; i < 2048; i += 512) hbuf[i] = 0.f;

    float b1init = (qt == 0) ? (bih1[rowg] + bhh1[rowg]) : 0.f;

    int half = (tid >> 7) & 1;
    int q = (tid >> 5) & 3, j = tid & 31;
    int hl = (r << 5) + j;
    bool ew = (tid < 256);
    float cst = 0.f, pool = 0.f;

    float xn[4];
    if (qt == 0) {
#pragma unroll
        for (int bb = 0; bb < 4; bb++)
            xn[bb] = g_x0[((size_t)(b0 + bb) * Tt) * Gg + rowg];
    }

    uint32_t hb_la = (uint32_t)__cvta_generic_to_shared(hbuf);
    uint32_t rb[4];
#pragma unroll
    for (int rk = 0; rk < 4; rk++)
        asm("mapa.shared::cluster.u32 %0, %1, %2;" : "=r"(rb[rk]) : "r"(hb_la), "r"(rk));

    __syncthreads();
    asm volatile("barrier.cluster.arrive.aligned;" ::: "memory");
    asm volatile("barrier.cluster.wait.aligned;"   ::: "memory");

    const uint4* wr0 = reinterpret_cast<const uint4*>(w0 + lr * WROW + qt * 16);
    const uint4* wr1 = reinterpret_cast<const uint4*>(w1 + lr * WROW + qt * 16);
    const uint4* wr2 = reinterpret_cast<const uint4*>(w2 + lr * WROW + qt * 16);

    int p = 0;
    for (int t = 0; t <= Tt; t++) {
        const float* hcur = hbuf + p * 1024 + qt * 32;
        unsigned long long accA[4], accB[4];
#pragma unroll
        for (int bb = 0; bb < 4; bb++) {
            accA[bb] = pack2(qt == 0 ? xn[bb] : 0.f, 0.f);
            accB[bb] = pack2(b1init, 0.f);
        }
#pragma unroll
        for (int kq = 0; kq < 4; kq++) {
            uint4 p0 = wr0[kq], p1 = wr1[kq];
            unsigned long long w0a = bf2f2(p0.x), w0b = bf2f2(p0.y),
                               w0c = bf2f2(p0.z), w0d = bf2f2(p0.w);
            unsigned long long w1a = bf2f2(p1.x), w1b = bf2f2(p1.y),
                               w1c = bf2f2(p1.z), w1d = bf2f2(p1.w);
#pragma unroll
            for (int bb = 0; bb < 4; bb++) {
                const ulonglong2* hp = reinterpret_cast<const ulonglong2*>(hcur + bb * 128) + kq * 2;
                ulonglong2 h01 = hp[0], h23 = hp[1];
                accA[bb] = fma2(w0a, h01.x, accA[bb]);
                accA[bb] = fma2(w0b, h01.y, accA[bb]);
                accA[bb] = fma2(w0c, h23.x, accA[bb]);
                accA[bb] = fma2(w0d, h23.y, accA[bb]);
                accB[bb] = fma2(w1a, h01.x, accB[bb]);
                accB[bb] = fma2(w1b, h01.y, accB[bb]);
                accB[bb] = fma2(w1c, h23.x, accB[bb]);
                accB[bb] = fma2(w1d, h23.y, accB[bb]);
            }
        }
#pragma unroll
        for (int kq = 0; kq < 4; kq++) {
            uint4 p2 = wr2[kq];
            unsigned long long w2a = bf2f2(p2.x), w2b = bf2f2(p2.y),
                               w2c = bf2f2(p2.z), w2d = bf2f2(p2.w);
#pragma unroll
            for (int bb = 0; bb < 4; bb++) {
                const ulonglong2* hp =
                    reinterpret_cast<const ulonglong2*>(hcur + 512 + bb * 128) + kq * 2;
                ulonglong2 h01 = hp[0], h23 = hp[1];
                accB[bb] = fma2(w2a, h01.x, accB[bb]);
                accB[bb] = fma2(w2b, h01.y, accB[bb]);
                accB[bb] = fma2(w2c, h23.x, accB[bb]);
                accB[bb] = fma2(w2d, h23.y, accB[bb]);
            }
        }
        if (t < Tt) {
#pragma unroll
            for (int bb = 0; bb < 4; bb++)
                gtmp[(bb << 9) + (qt << 7) + lr] = sum2(accA[bb]);
        }
        if (t > 0) {
#pragma unroll
            for (int bb = 0; bb < 4; bb++)
                gtmp[2048 + (bb << 9) + (qt << 7) + lr] = sum2(accB[bb]);
        }
        __syncthreads();
        bool act = ew && ((half == 0) ? (t < Tt) : (t > 0));
        if (act) {
            int gb = half * 2048 + (q << 9);
            float gv[4];
#pragma unroll
            for (int g = 0; g < 4; g++) {
                int ro = (g << 5) + j;
                gv[g] = (gtmp[gb + ro] + gtmp[gb + 128 + ro])
                      + (gtmp[gb + 256 + ro] + gtmp[gb + 384 + ro]);
            }
            float cn = sig_fast(gv[1]) * cst + sig_fast(gv[0]) * tanh_fast(gv[2]);
            float hn = sig_fast(gv[3]) * tanh_fast(cn);
            cst = cn;
            if (half) pool += hn;
            uint32_t off = (uint32_t)((((p ^ 1) << 10) + (half << 9) + (q << 7) + hl) << 2);
#pragma unroll
            for (int rk = 0; rk < 4; rk++)
                asm volatile("st.shared::cluster.f32 [%0], %1;"
                             :: "r"(rb[rk] + off), "f"(hn) : "memory");
        }
        asm volatile("barrier.cluster.arrive.aligned;" ::: "memory");
        if (qt == 0 && t + 1 < Tt) {
#pragma unroll
            for (int bb = 0; bb < 4; bb++)
                xn[bb] = g_x0[((size_t)(b0 + bb) * Tt + (t + 1)) * Gg + rowg];
        }
        asm volatile("barrier.cluster.wait.aligned;" ::: "memory");
        p ^= 1;
    }
    if (ew && half == 1)
        g_pooled[(size_t)(b0 + q) * Hh + hl] = pool * (1.0f / 2048.0f);
}

// ============================ kernel 4: out[b] = pooled[b,:] . lin_w + lin_b ============================
__global__ void final_kernel(const float* __restrict__ lw, const float* __restrict__ lb,
                             float* __restrict__ out) {
    int b = threadIdx.x;
    float acc = lb[0];
#pragma unroll 8
    for (int h = 0; h < Hh; h++) acc += g_pooled[b * Hh + h] * lw[h];
    out[b] = acc;
}

// ============================ launch ============================
extern "C" void kernel_launch(void* const* d_in, const int* in_sizes, int n_in,
                              void* d_out, int out_size) {
    (void)in_sizes; (void)n_in; (void)out_size;
    const float* x      = (const float*)d_in[0];
    const float* conv_w = (const float*)d_in[1];
    const float* conv_b = (const float*)d_in[2];
    const float* w_ih0  = (const float*)d_in[3];
    const float* w_hh0  = (const float*)d_in[4];
    const float* b_ih0  = (const float*)d_in[5];
    const float* b_hh0  = (const float*)d_in[6];
    const float* w_ih1  = (const float*)d_in[7];
    const float* w_hh1  = (const float*)d_in[8];
    const float* b_ih1  = (const float*)d_in[9];
    const float* b_hh1  = (const float*)d_in[10];
    const float* lin_w  = (const float*)d_in[11];
    const float* lin_b  = (const float*)d_in[12];
    float* out = (float*)d_out;

    cudaFuncSetAttribute(proj_kernel, cudaFuncAttributeMaxDynamicSharedMemorySize, PROJ_SMEM_BYTES);
    cudaFuncSetAttribute(lstm_kernel, cudaFuncAttributeMaxDynamicSharedMemorySize, LSTM_SMEM_BYTES);

    conv_kernel<<<dim3(Tt / 128, Bsz), 256>>>(x, conv_w, conv_b);
    prep_kernel<<<128, 256>>>(w_ih0, b_ih0, b_hh0);
    proj_kernel<<<dim3((Bsz * Tt) / 128, Gg / 64), 256, PROJ_SMEM_BYTES>>>();
    lstm_kernel<<<128, 512, LSTM_SMEM_BYTES>>>(w_hh0, w_ih1, w_hh1, b_ih1, b_hh1);
    final_kernel<<<1, 128>>>(lin_w, lin_b, out);
}

// round 17
// speedup vs baseline: 1.3254x; 1.0537x over previous
#include <cuda_runtime.h>
#include <cstdint>
#include <cstddef>

#define Bsz 128
#define Tt  2048
#define Cin 16
#define CO  128
#define Hh  128
#define Gg  512

// -------- scratch (no allocations allowed; __device__ globals are the sanctioned path) ------
__device__ uint32_t g_seq16[(size_t)Bsz * Tt * 64];   // conv output, f16x2 pairs [b*T+t][co/2]
__device__ uint32_t g_w16[Gg * 64];                   // w_ih0 as f16x2 [g][k/2]
__device__ float    g_bsum[Gg];                       // b_ih0 + b_hh0
__device__ float g_x0 [(size_t)Bsz * Tt * Gg];        // layer-0 input projection, [b*T+t][g]
__device__ float g_pooled[Bsz * Hh];                  // mean over t of h1

// ---------------- packed f32x2 helpers ----------------
__device__ __forceinline__ unsigned long long fma2(unsigned long long a, unsigned long long b,
                                                   unsigned long long c) {
    unsigned long long d;
    asm("fma.rn.f32x2 %0, %1, %2, %3;" : "=l"(d) : "l"(a), "l"(b), "l"(c));
    return d;
}
__device__ __forceinline__ unsigned long long pack2(float lo, float hi) {
    unsigned long long r;
    asm("mov.b64 %0, {%1, %2};" : "=l"(r) : "f"(lo), "f"(hi));
    return r;
}
__device__ __forceinline__ void unpack2(unsigned long long v, float& a, float& b) {
    asm("mov.b64 {%0, %1}, %2;" : "=f"(a), "=f"(b) : "l"(v));
}
__device__ __forceinline__ float sum2(unsigned long long v) {
    float a, b; unpack2(v, a, b); return a + b;
}
// expand packed bf16x2 into f32x2 {w[k], w[k+1]}
__device__ __forceinline__ unsigned long long bf2f2(uint32_t p) {
    uint32_t lo = p << 16;
    uint32_t hi = p & 0xFFFF0000u;
    unsigned long long r;
    asm("mov.b64 %0, {%1, %2};" : "=l"(r) : "r"(lo), "r"(hi));
    return r;
}
// pack two fp32 into bf16x2: low16 = bf16(a), high16 = bf16(b)
__device__ __forceinline__ uint32_t f2bf2(float a, float b) {
    uint32_t r;
    asm("cvt.rn.bf16x2.f32 %0, %1, %2;" : "=r"(r) : "f"(b), "f"(a));
    return r;
}
// pack two fp32 into f16x2: low16 = f16(a), high16 = f16(b)
__device__ __forceinline__ uint32_t f2h2(float a, float b) {
    uint32_t r;
    asm("cvt.rn.f16x2.f32 %0, %1, %2;" : "=r"(r) : "f"(b), "f"(a));
    return r;
}

// ============================ kernel 1: conv1d(k=3,pad=1) + LeakyReLU -> f16 ============================
__global__ void conv_kernel(const float* __restrict__ x, const float* __restrict__ cw,
                            const float* __restrict__ cb) {
    __shared__ float xs[130 * 16];     // t0-1 .. t0+128
    __shared__ float wct[48 * 128];    // [(c*3+kk)][co]
    __shared__ float cbs[128];
    int tid = threadIdx.x;
    int b = blockIdx.y, t0 = blockIdx.x * 128;
    for (int i = tid; i < 130 * 16; i += 256) {
        int row = i >> 4, c = i & 15;
        int t = t0 - 1 + row;
        xs[i] = (t >= 0 && t < Tt) ? x[((size_t)b * Tt + t) * Cin + c] : 0.0f;
    }
    for (int i = tid; i < 48 * 128; i += 256) {
        int co = i / 48, rem = i % 48;          // rem = c*3 + kk
        wct[rem * 128 + co] = cw[i];
    }
    if (tid < 128) cbs[tid] = cb[tid];
    __syncthreads();
    for (int idx = tid; idx < 128 * 64; idx += 256) {
        int tl = idx >> 6, cp = idx & 63;
        int co0 = 2 * cp, co1 = 2 * cp + 1;
        float a0 = cbs[co0], a1 = cbs[co1];
#pragma unroll
        for (int c = 0; c < 16; c++)
#pragma unroll
            for (int kk = 0; kk < 3; kk++) {
                float xv = xs[(tl + kk) * 16 + c];
                a0 += xv * wct[(c * 3 + kk) * 128 + co0];
                a1 += xv * wct[(c * 3 + kk) * 128 + co1];
            }
        a0 = a0 >= 0.f ? a0 : 0.01f * a0;
        a1 = a1 >= 0.f ? a1 : 0.01f * a1;
        g_seq16[((size_t)b * Tt + t0 + tl) * 64 + cp] = f2h2(a0, a1);
    }
}

// ============================ kernel 1b: w_ih0 -> f16, bias sum ============================
__global__ void prep_kernel(const float* __restrict__ w, const float* __restrict__ bi,
                            const float* __restrict__ bh) {
    int i = blockIdx.x * 256 + threadIdx.x;      // 0 .. 32767
    if (i < Gg * 64) {
        int n = i >> 6, cp = i & 63;
        const float* s = w + (size_t)n * CO + 2 * cp;
        g_w16[i] = f2h2(s[0], s[1]);
    }
    if (i < Gg) g_bsum[i] = bi[i] + bh[i];
}

// ============================ kernel 2: x0 = seq @ w_ih0^T + bsum  (HMMA) ============================
#define PROJ_SMEM_BYTES ((128 * 68 + 64 * 68) * 4 + 256)
__global__ void proj_kernel(void) {
    extern __shared__ uint32_t smu[];
    uint32_t* As = smu;                      // [128][68]
    uint32_t* Ws = smu + 128 * 68;           // [64][68]
    float* bsum_s = reinterpret_cast<float*>(smu + 128 * 68 + 64 * 68);
    int tid = threadIdx.x;
    int mt = blockIdx.x, nt = blockIdx.y;

    const uint4* a4 = reinterpret_cast<const uint4*>(g_seq16 + (size_t)mt * 128 * 64);
    for (int i = tid; i < 128 * 16; i += 256) {
        int row = i >> 4, c4 = i & 15;
        uint4 v = a4[row * 16 + c4];
        uint32_t* d = As + row * 68 + c4 * 4;
        d[0] = v.x; d[1] = v.y; d[2] = v.z; d[3] = v.w;
    }
    const uint4* w4 = reinterpret_cast<const uint4*>(g_w16 + (size_t)nt * 64 * 64);
    for (int i = tid; i < 64 * 16; i += 256) {
        int row = i >> 4, c4 = i & 15;
        uint4 v = w4[row * 16 + c4];
        uint32_t* d = Ws + row * 68 + c4 * 4;
        d[0] = v.x; d[1] = v.y; d[2] = v.z; d[3] = v.w;
    }
    if (tid < 64) bsum_s[tid] = g_bsum[nt * 64 + tid];
    __syncthreads();

    int lane = tid & 31, wid = tid >> 5;
    int wm = (wid & 3) * 32, wn = (wid >> 2) * 32;
    uint32_t as_b = (uint32_t)__cvta_generic_to_shared(As);
    uint32_t ws_b = (uint32_t)__cvta_generic_to_shared(Ws);
    uint32_t a_ad[2];
#pragma unroll
    for (int mf = 0; mf < 2; mf++)
        a_ad[mf] = as_b + (wm + mf * 16 + (lane & 15)) * 272 + (lane >> 4) * 16;
    uint32_t b_ad[4];
#pragma unroll
    for (int nf = 0; nf < 4; nf++)
        b_ad[nf] = ws_b + (wn + nf * 8 + (lane & 7)) * 272 + ((lane >> 3) & 1) * 16;

    float acc[2][4][4];
#pragma unroll
    for (int mf = 0; mf < 2; mf++)
#pragma unroll
        for (int nf = 0; nf < 4; nf++)
#pragma unroll
            for (int i = 0; i < 4; i++) acc[mf][nf][i] = 0.f;

#pragma unroll
    for (int ks = 0; ks < 8; ks++) {
        uint32_t a[2][4];
#pragma unroll
        for (int mf = 0; mf < 2; mf++)
            asm volatile("ldmatrix.sync.aligned.m8n8.x4.shared.b16 {%0,%1,%2,%3}, [%4];"
                         : "=r"(a[mf][0]), "=r"(a[mf][1]), "=r"(a[mf][2]), "=r"(a[mf][3])
                         : "r"(a_ad[mf] + ks * 32));
        uint32_t bf[4][2];
#pragma unroll
        for (int nf = 0; nf < 4; nf++)
            asm volatile("ldmatrix.sync.aligned.m8n8.x2.shared.b16 {%0,%1}, [%2];"
                         : "=r"(bf[nf][0]), "=r"(bf[nf][1])
                         : "r"(b_ad[nf] + ks * 32));
#pragma unroll
        for (int mf = 0; mf < 2; mf++)
#pragma unroll
            for (int nf = 0; nf < 4; nf++)
                asm volatile(
                    "mma.sync.aligned.m16n8k16.row.col.f32.f16.f16.f32 "
                    "{%0,%1,%2,%3}, {%4,%5,%6,%7}, {%8,%9}, {%0,%1,%2,%3};"
                    : "+f"(acc[mf][nf][0]), "+f"(acc[mf][nf][1]),
                      "+f"(acc[mf][nf][2]), "+f"(acc[mf][nf][3])
                    : "r"(a[mf][0]), "r"(a[mf][1]), "r"(a[mf][2]), "r"(a[mf][3]),
                      "r"(bf[nf][0]), "r"(bf[nf][1]));
    }

    int g = lane >> 2, t = lane & 3;
#pragma unroll
    for (int mf = 0; mf < 2; mf++) {
        int row0 = mt * 128 + wm + mf * 16 + g;
#pragma unroll
        for (int nf = 0; nf < 4; nf++) {
            int nl = wn + nf * 8 + t * 2;
            float b0 = bsum_s[nl], b1 = bsum_s[nl + 1];
            int nglob = nt * 64 + nl;
            float2 v0 = { acc[mf][nf][0] + b0, acc[mf][nf][1] + b1 };
            float2 v1 = { acc[mf][nf][2] + b0, acc[mf][nf][3] + b1 };
            *reinterpret_cast<float2*>(g_x0 + (size_t)row0 * Gg + nglob) = v0;
            *reinterpret_cast<float2*>(g_x0 + (size_t)(row0 + 8) * Gg + nglob) = v1;
        }
    }
}

// ============================ kernel 3: persistent 2-layer LSTM, cluster-of-4 ============================
// 32 clusters x 4 CTAs, 256 threads/CTA. Cluster owns 4 batch rows; CTA r owns gate
// rows {g*128 + r*32 + j}. GEMM role: each thread owns TWO rows (row1, row1+64) and a
// k-quarter s (32 k). Warp layout: lanes 0-15 carry s, lanes 16-31 carry s+1, same 16
// rows -> every h LDS serves a 2-way broadcast in one phase (h crossbar halved), and
// the two s-partials combine via shfl.bfly(16)+add (gtmp: 2 partials/row).
// Weights bf16x2 in smem (ALU expand), fp32 fma2 accumulate, fused h0 pass.

__device__ __forceinline__ float tanh_fast(float x) {
    float y; asm("tanh.approx.f32 %0, %1;" : "=f"(y) : "f"(x)); return y;
}
__device__ __forceinline__ float sig_fast(float x) {
    return fmaf(tanh_fast(0.5f * x), 0.5f, 0.5f);
}

#define WROW 68
// smem: weights 3*128*68 u32 | hbuf 2048 f32 | gtmp 2048 f32 ([2 L][4 bb][2 sp][128 row])
#define LSTM_SMEM_BYTES ((3 * 128 * WROW + 2048 + 2048) * 4)

__global__ void __cluster_dims__(4, 1, 1) __launch_bounds__(256, 1)
lstm_kernel(const float* __restrict__ whh0, const float* __restrict__ wih1,
            const float* __restrict__ whh1, const float* __restrict__ bih1,
            const float* __restrict__ bhh1) {
    extern __shared__ float sm[];
    uint32_t* w0 = reinterpret_cast<uint32_t*>(sm);          // W_hh0 slice [128 rows][WROW]
    uint32_t* w1 = w0 + 128 * WROW;                          // W_ih1 slice
    uint32_t* w2 = w1 + 128 * WROW;                          // W_hh1 slice
    float* hbuf = sm + 3 * 128 * WROW;                       // [2 p][2 layer][4 bb][128 k]
    float* gtmp = hbuf + 2048;                               // [2 L][4 bb][2 sp][128 row]

    int tid = threadIdx.x;
    int lane = tid & 31, wp = tid >> 5;          // 8 warps
    uint32_t rank; asm("mov.u32 %0, %%cluster_ctarank;" : "=r"(rank));
    int r = (int)rank;
    int b0 = (blockIdx.x >> 2) * 4;

    // GEMM role: rows row1, row1+64; k-quarter s4
    int s4   = ((wp >> 2) << 1) | (lane >> 4);   // 0..3
    int sp   = wp >> 2;                          // s-pair id (0,1)
    int row1 = ((wp & 3) << 4) | (lane & 15);    // 0..63
    int row2 = row1 + 64;
    int rg1 = ((row1 >> 5) << 7) + (r << 5) + (row1 & 31);   // global gate rows
    int rg2 = ((row2 >> 5) << 7) + (r << 5) + (row2 & 31);

    // load weight slices, converting fp32 -> packed bf16x2
    for (int i = tid; i < 128 * 64; i += 256) {
        int rl = i >> 6, c = i & 63;
        int rg = ((rl >> 5) << 7) + (r << 5) + (rl & 31);
        size_t gb = (size_t)rg * Hh + 2 * c;
        w0[rl * WROW + c] = f2bf2(whh0[gb], whh0[gb + 1]);
        w1[rl * WROW + c] = f2bf2(wih1[gb], wih1[gb + 1]);
        w2[rl * WROW + c] = f2bf2(whh1[gb], whh1[gb + 1]);
    }
    for (int i = tid; i < 2048; i += 256) hbuf[i] = 0.f;

    bool s0 = (s4 == 0);
    float b1a = s0 ? (bih1[rg1] + bhh1[rg1]) : 0.f;
    float b1b = s0 ? (bih1[rg2] + bhh1[rg2]) : 0.f;

    // elementwise role: all 256 threads: (layer=half, batch=q, h=hl)
    int half = (tid >> 7) & 1;
    int q = (tid >> 5) & 3, j = tid & 31;
    int hl = (r << 5) + j;
    float cst = 0.f, pool = 0.f;

    float xn1[4], xn2[4];
    if (s0) {
#pragma unroll
        for (int bb = 0; bb < 4; bb++) {
            xn1[bb] = g_x0[((size_t)(b0 + bb) * Tt) * Gg + rg1];
            xn2[bb] = g_x0[((size_t)(b0 + bb) * Tt) * Gg + rg2];
        }
    }

    uint32_t hb_la = (uint32_t)__cvta_generic_to_shared(hbuf);
    uint32_t rb[4];
#pragma unroll
    for (int rk = 0; rk < 4; rk++)
        asm("mapa.shared::cluster.u32 %0, %1, %2;" : "=r"(rb[rk]) : "r"(hb_la), "r"(rk));

    __syncthreads();
    asm volatile("barrier.cluster.arrive.aligned;" ::: "memory");
    asm volatile("barrier.cluster.wait.aligned;"   ::: "memory");

    // weight row-quarter pointers: 4 uint4 per (matrix, row)
    const uint4* w0a = reinterpret_cast<const uint4*>(w0 + row1 * WROW + s4 * 16);
    const uint4* w0b = reinterpret_cast<const uint4*>(w0 + row2 * WROW + s4 * 16);
    const uint4* w1a = reinterpret_cast<const uint4*>(w1 + row1 * WROW + s4 * 16);
    const uint4* w1b = reinterpret_cast<const uint4*>(w1 + row2 * WROW + s4 * 16);
    const uint4* w2a = reinterpret_cast<const uint4*>(w2 + row1 * WROW + s4 * 16);
    const uint4* w2b = reinterpret_cast<const uint4*>(w2 + row2 * WROW + s4 * 16);

    int p = 0;
    for (int t = 0; t <= Tt; t++) {
        const float* hcur = hbuf + p * 1024 + s4 * 32;   // layer0 h (+512 -> layer1)
        unsigned long long aA1[4], aA2[4], aB1[4], aB2[4];
#pragma unroll
        for (int bb = 0; bb < 4; bb++) {
            aA1[bb] = pack2(s0 ? xn1[bb] : 0.f, 0.f);
            aA2[bb] = pack2(s0 ? xn2[bb] : 0.f, 0.f);
            aB1[bb] = pack2(b1a, 0.f);
            aB2[bb] = pack2(b1b, 0.f);
        }
        // ---- fused h0 pass: aA += W_hh0.h0 ; aB += W_ih1.h0 (h shared across 2 rows, 2 mats)
#pragma unroll
        for (int kq = 0; kq < 4; kq++) {
            uint4 p0a = w0a[kq], p0b = w0b[kq], p1a = w1a[kq], p1b = w1b[kq];
            unsigned long long e0a[4] = { bf2f2(p0a.x), bf2f2(p0a.y), bf2f2(p0a.z), bf2f2(p0a.w) };
            unsigned long long e0b[4] = { bf2f2(p0b.x), bf2f2(p0b.y), bf2f2(p0b.z), bf2f2(p0b.w) };
            unsigned long long e1a[4] = { bf2f2(p1a.x), bf2f2(p1a.y), bf2f2(p1a.z), bf2f2(p1a.w) };
            unsigned long long e1b[4] = { bf2f2(p1b.x), bf2f2(p1b.y), bf2f2(p1b.z), bf2f2(p1b.w) };
#pragma unroll
            for (int bb = 0; bb < 4; bb++) {
                const ulonglong2* hp = reinterpret_cast<const ulonglong2*>(hcur + bb * 128) + kq * 2;
                ulonglong2 h01 = hp[0], h23 = hp[1];
                aA1[bb] = fma2(e0a[0], h01.x, aA1[bb]);
                aA1[bb] = fma2(e0a[1], h01.y, aA1[bb]);
                aA1[bb] = fma2(e0a[2], h23.x, aA1[bb]);
                aA1[bb] = fma2(e0a[3], h23.y, aA1[bb]);
                aA2[bb] = fma2(e0b[0], h01.x, aA2[bb]);
                aA2[bb] = fma2(e0b[1], h01.y, aA2[bb]);
                aA2[bb] = fma2(e0b[2], h23.x, aA2[bb]);
                aA2[bb] = fma2(e0b[3], h23.y, aA2[bb]);
                aB1[bb] = fma2(e1a[0], h01.x, aB1[bb]);
                aB1[bb] = fma2(e1a[1], h01.y, aB1[bb]);
                aB1[bb] = fma2(e1a[2], h23.x, aB1[bb]);
                aB1[bb] = fma2(e1a[3], h23.y, aB1[bb]);
                aB2[bb] = fma2(e1b[0], h01.x, aB2[bb]);
                aB2[bb] = fma2(e1b[1], h01.y, aB2[bb]);
                aB2[bb] = fma2(e1b[2], h23.x, aB2[bb]);
                aB2[bb] = fma2(e1b[3], h23.y, aB2[bb]);
            }
        }
        // ---- h1 pass: aB += W_hh1 . h1
#pragma unroll
        for (int kq = 0; kq < 4; kq++) {
            uint4 p2a = w2a[kq], p2b = w2b[kq];
            unsigned long long e2a[4] = { bf2f2(p2a.x), bf2f2(p2a.y), bf2f2(p2a.z), bf2f2(p2a.w) };
            unsigned long long e2b[4] = { bf2f2(p2b.x), bf2f2(p2b.y), bf2f2(p2b.z), bf2f2(p2b.w) };
#pragma unroll
            for (int bb = 0; bb < 4; bb++) {
                const ulonglong2* hp =
                    reinterpret_cast<const ulonglong2*>(hcur + 512 + bb * 128) + kq * 2;
                ulonglong2 h01 = hp[0], h23 = hp[1];
                aB1[bb] = fma2(e2a[0], h01.x, aB1[bb]);
                aB1[bb] = fma2(e2a[1], h01.y, aB1[bb]);
                aB1[bb] = fma2(e2a[2], h23.x, aB1[bb]);
                aB1[bb] = fma2(e2a[3], h23.y, aB1[bb]);
                aB2[bb] = fma2(e2b[0], h01.x, aB2[bb]);
                aB2[bb] = fma2(e2b[1], h01.y, aB2[bb]);
                aB2[bb] = fma2(e2b[2], h23.x, aB2[bb]);
                aB2[bb] = fma2(e2b[3], h23.y, aB2[bb]);
            }
        }
        // ---- combine s-pairs via shfl (lane^16 = same rows, partner quarter), store 2 partials
        bool lo16 = (lane < 16);
        if (t < Tt) {
#pragma unroll
            for (int bb = 0; bb < 4; bb++) {
                float v1 = sum2(aA1[bb]); v1 += __shfl_xor_sync(0xffffffffu, v1, 16);
                float v2 = sum2(aA2[bb]); v2 += __shfl_xor_sync(0xffffffffu, v2, 16);
                if (lo16) {
                    gtmp[((bb << 1) + sp) * 128 + row1] = v1;
                    gtmp[((bb << 1) + sp) * 128 + row2] = v2;
                }
            }
        }
        if (t > 0) {
#pragma unroll
            for (int bb = 0; bb < 4; bb++) {
                float v1 = sum2(aB1[bb]); v1 += __shfl_xor_sync(0xffffffffu, v1, 16);
                float v2 = sum2(aB2[bb]); v2 += __shfl_xor_sync(0xffffffffu, v2, 16);
                if (lo16) {
                    gtmp[1024 + ((bb << 1) + sp) * 128 + row1] = v1;
                    gtmp[1024 + ((bb << 1) + sp) * 128 + row2] = v2;
                }
            }
        }
        __syncthreads();
        // ---- elementwise: thread owns (layer=half, batch=q, h=hl); 2-partial gather
        bool act = (half == 0) ? (t < Tt) : (t > 0);
        if (act) {
            int gb = half * 1024 + (q << 8);    // gtmp base for (layer, batch): [bb][2 sp][128]
            float gv[4];
#pragma unroll
            for (int g = 0; g < 4; g++) {
                int ro = (g << 5) + j;
                gv[g] = gtmp[gb + ro] + gtmp[gb + 128 + ro];
            }
            float cn = sig_fast(gv[1]) * cst + sig_fast(gv[0]) * tanh_fast(gv[2]);
            float hn = sig_fast(gv[3]) * tanh_fast(cn);
            cst = cn;
            if (half) pool += hn;
            uint32_t off = (uint32_t)((((p ^ 1) << 10) + (half << 9) + (q << 7) + hl) << 2);
#pragma unroll
            for (int rk = 0; rk < 4; rk++)
                asm volatile("st.shared::cluster.f32 [%0], %1;"
                             :: "r"(rb[rk] + off), "f"(hn) : "memory");
        }
        asm volatile("barrier.cluster.arrive.aligned;" ::: "memory");
        if (s0 && t + 1 < Tt) {
#pragma unroll
            for (int bb = 0; bb < 4; bb++) {
                xn1[bb] = g_x0[((size_t)(b0 + bb) * Tt + (t + 1)) * Gg + rg1];
                xn2[bb] = g_x0[((size_t)(b0 + bb) * Tt + (t + 1)) * Gg + rg2];
            }
        }
        asm volatile("barrier.cluster.wait.aligned;" ::: "memory");
        p ^= 1;
    }
    if (half == 1)
        g_pooled[(size_t)(b0 + q) * Hh + hl] = pool * (1.0f / 2048.0f);
}

// ============================ kernel 4: out[b] = pooled[b,:] . lin_w + lin_b ============================
__global__ void final_kernel(const float* __restrict__ lw, const float* __restrict__ lb,
                             float* __restrict__ out) {
    int b = threadIdx.x;
    float acc = lb[0];
#pragma unroll 8
    for (int h = 0; h < Hh; h++) acc += g_pooled[b * Hh + h] * lw[h];
    out[b] = acc;
}

// ============================ launch ============================
extern "C" void kernel_launch(void* const* d_in, const int* in_sizes, int n_in,
                              void* d_out, int out_size) {
    (void)in_sizes; (void)n_in; (void)out_size;
    const float* x      = (const float*)d_in[0];
    const float* conv_w = (const float*)d_in[1];
    const float* conv_b = (const float*)d_in[2];
    const float* w_ih0  = (const float*)d_in[3];
    const float* w_hh0  = (const float*)d_in[4];
    const float* b_ih0  = (const float*)d_in[5];
    const float* b_hh0  = (const float*)d_in[6];
    const float* w_ih1  = (const float*)d_in[7];
    const float* w_hh1  = (const float*)d_in[8];
    const float* b_ih1  = (const float*)d_in[9];
    const float* b_hh1  = (const float*)d_in[10];
    const float* lin_w  = (const float*)d_in[11];
    const float* lin_b  = (const float*)d_in[12];
    float* out = (float*)d_out;

    cudaFuncSetAttribute(proj_kernel, cudaFuncAttributeMaxDynamicSharedMemorySize, PROJ_SMEM_BYTES);
    cudaFuncSetAttribute(lstm_kernel, cudaFuncAttributeMaxDynamicSharedMemorySize, LSTM_SMEM_BYTES);

    conv_kernel<<<dim3(Tt / 128, Bsz), 256>>>(x, conv_w, conv_b);
    prep_kernel<<<128, 256>>>(w_ih0, b_ih0, b_hh0);
    proj_kernel<<<dim3((Bsz * Tt) / 128, Gg / 64), 256, PROJ_SMEM_BYTES>>>();
    lstm_kernel<<<128, 256, LSTM_SMEM_BYTES>>>(w_hh0, w_ih1, w_hh1, b_ih1, b_hh1);
    final_kernel<<<1, 128>>>(lin_w, lin_b, out);
}